// round 4
// baseline (speedup 1.0000x reference)
#include <cuda_runtime.h>

#define N_NODES 50000
#define N_EDGES 800000
#define IN_F 96
#define HID 64
#define N_CLS 32

// Scratch (__device__ globals, allocation-free rule)
__device__ __align__(16) float g_y[N_NODES * HID];      // x @ W1       (12.8 MB)
__device__ __align__(16) float g_z[N_NODES * N_CLS];    // relu(.)@W2   ( 6.4 MB)
__device__ int g_cnt[N_NODES];
__device__ int g_off[N_NODES + 1];
__device__ int g_cur[N_NODES];
__device__ int g_ssrc[N_EDGES];

// ---------------- CSR build ----------------

__global__ void zero_cnt_kernel() {
    int i = blockIdx.x * blockDim.x + threadIdx.x;
    if (i < N_NODES) g_cnt[i] = 0;
}

__global__ void hist_kernel(const int* __restrict__ dst) {
    int i = blockIdx.x * blockDim.x + threadIdx.x;
    if (i < N_EDGES) atomicAdd(&g_cnt[dst[i]], 1);
}

// Single-block exclusive scan of g_cnt -> g_off, g_cur. blockDim = 1024.
__global__ void scan_kernel() {
    __shared__ int sh[1024];
    const int C = (N_NODES + 1023) / 1024;   // 49
    int t = threadIdx.x;
    int base = t * C;
    int s = 0;
    for (int j = 0; j < C; ++j) {
        int idx = base + j;
        if (idx < N_NODES) s += g_cnt[idx];
    }
    sh[t] = s;
    __syncthreads();
    for (int o = 1; o < 1024; o <<= 1) {
        int v = (t >= o) ? sh[t - o] : 0;
        __syncthreads();
        sh[t] += v;
        __syncthreads();
    }
    int run = sh[t] - s;   // exclusive prefix of this thread's chunk
    for (int j = 0; j < C; ++j) {
        int idx = base + j;
        if (idx < N_NODES) {
            int c = g_cnt[idx];
            g_off[idx] = run;
            g_cur[idx] = run;
            run += c;
        }
    }
    if (t == 1023) g_off[N_NODES] = N_EDGES;
}

__global__ void reorder_kernel(const int* __restrict__ src,
                               const int* __restrict__ dst) {
    int i = blockIdx.x * blockDim.x + threadIdx.x;
    if (i < N_EDGES) {
        int pos = atomicAdd(&g_cur[dst[i]], 1);
        g_ssrc[pos] = src[i];
    }
}

// ---------------- compute ----------------

// y = x @ W1  [50000 x 64]. 4 nodes per 256-thread block, thread j -> y[n][j].
__global__ void gemm_x_kernel(const float* __restrict__ x,
                              const float* __restrict__ W1,
                              float* __restrict__ Y) {
    __shared__ float Ws[IN_F * HID];
    for (int i = threadIdx.x; i < IN_F * HID; i += 256) Ws[i] = W1[i];
    __syncthreads();
    int j = threadIdx.x & (HID - 1);
    int n = blockIdx.x * 4 + (threadIdx.x >> 6);
    const float* a = x + n * IN_F;
    float acc = 0.f;
#pragma unroll
    for (int k = 0; k < IN_F; ++k) acc = fmaf(__ldg(a + k), Ws[k * HID + j], acc);
    Y[n * HID + j] = acc;
}

// Layer 1 fused: agg1[n] = sum over in-edges of y[src]; h = relu(agg1+b1);
// z[n] = h @ W2.   One warp per node, 8 nodes per 256-thread block.
// Gather: lanes split into 2 halves; half processes alternate edges,
// 16 lanes x float4 = 64 floats per edge.
__global__ void layer1_kernel(const float* __restrict__ b1,
                              const float* __restrict__ W2,
                              float* __restrict__ Z) {
    __shared__ float Ws[HID * N_CLS];     // 8 KB
    __shared__ float b1s[HID];
    __shared__ float4 hs[8][16];          // per-warp hidden vector
    for (int i = threadIdx.x; i < HID * N_CLS; i += 256) Ws[i] = W2[i];
    if (threadIdx.x < HID) b1s[threadIdx.x] = b1[threadIdx.x];
    __syncthreads();

    int lane = threadIdx.x & 31;
    int w = threadIdx.x >> 5;
    int n = blockIdx.x * 8 + w;
    int half = lane >> 4;
    int col = lane & 15;

    int start = g_off[n], end = g_off[n + 1];
    const float4* y4 = (const float4*)g_y;
    float4 acc = make_float4(0.f, 0.f, 0.f, 0.f);
    for (int e = start + half; e < end; e += 2) {
        int s = __ldg(g_ssrc + e);
        float4 v = __ldg(y4 + s * 16 + col);
        acc.x += v.x; acc.y += v.y; acc.z += v.z; acc.w += v.w;
    }
    acc.x += __shfl_xor_sync(0xffffffffu, acc.x, 16);
    acc.y += __shfl_xor_sync(0xffffffffu, acc.y, 16);
    acc.z += __shfl_xor_sync(0xffffffffu, acc.z, 16);
    acc.w += __shfl_xor_sync(0xffffffffu, acc.w, 16);

    if (half == 0) {
        float4 bb = ((const float4*)b1s)[col];
        float4 h;
        h.x = fmaxf(acc.x + bb.x, 0.f);
        h.y = fmaxf(acc.y + bb.y, 0.f);
        h.z = fmaxf(acc.z + bb.z, 0.f);
        h.w = fmaxf(acc.w + bb.w, 0.f);
        hs[w][col] = h;
    }
    __syncwarp();

    const float* hf = (const float*)hs[w];
    float z = 0.f;
#pragma unroll
    for (int k = 0; k < HID; ++k) z = fmaf(hf[k], Ws[k * N_CLS + lane], z);
    Z[n * N_CLS + lane] = z;
}

// Layer 2 fused: agg2[n] = sum z[src]; out = log_softmax(agg2 + b2).
// One warp per node; lanes split into 4 quarters, 8 lanes x float4 = 32 floats/edge.
__global__ void layer2_kernel(const float* __restrict__ b2,
                              float* __restrict__ out) {
    int lane = threadIdx.x & 31;
    int w = threadIdx.x >> 5;
    int n = blockIdx.x * 8 + w;
    int q = lane >> 3;
    int col = lane & 7;

    int start = g_off[n], end = g_off[n + 1];
    const float4* z4 = (const float4*)g_z;
    float4 acc = make_float4(0.f, 0.f, 0.f, 0.f);
    for (int e = start + q; e < end; e += 4) {
        int s = __ldg(g_ssrc + e);
        float4 v = __ldg(z4 + s * 8 + col);
        acc.x += v.x; acc.y += v.y; acc.z += v.z; acc.w += v.w;
    }
#pragma unroll
    for (int o = 16; o >= 8; o >>= 1) {
        acc.x += __shfl_xor_sync(0xffffffffu, acc.x, o);
        acc.y += __shfl_xor_sync(0xffffffffu, acc.y, o);
        acc.z += __shfl_xor_sync(0xffffffffu, acc.z, o);
        acc.w += __shfl_xor_sync(0xffffffffu, acc.w, o);
    }
    float4 bb = __ldg(((const float4*)b2) + col);
    acc.x += bb.x; acc.y += bb.y; acc.z += bb.z; acc.w += bb.w;

    // log_softmax over 32 classes: col-major across lanes (bits 0-2 of lane)
    float m = fmaxf(fmaxf(acc.x, acc.y), fmaxf(acc.z, acc.w));
#pragma unroll
    for (int o = 1; o <= 4; o <<= 1) m = fmaxf(m, __shfl_xor_sync(0xffffffffu, m, o));
    float p = __expf(acc.x - m) + __expf(acc.y - m) + __expf(acc.z - m) + __expf(acc.w - m);
#pragma unroll
    for (int o = 1; o <= 4; o <<= 1) p += __shfl_xor_sync(0xffffffffu, p, o);
    float lp = m + __logf(p);

    if (lane < 8) {
        float4 r;
        r.x = acc.x - lp; r.y = acc.y - lp; r.z = acc.z - lp; r.w = acc.w - lp;
        ((float4*)out)[n * 8 + col] = r;
    }
}

extern "C" void kernel_launch(void* const* d_in, const int* in_sizes, int n_in,
                              void* d_out, int out_size) {
    const float* x  = (const float*)d_in[0];
    const int*   ei = (const int*)d_in[1];   // int32 [2, E]
    const float* W1 = (const float*)d_in[2];
    const float* b1 = (const float*)d_in[3];
    const float* W2 = (const float*)d_in[4];
    const float* b2 = (const float*)d_in[5];
    float* out      = (float*)d_out;

    const int* src = ei;
    const int* dst = ei + N_EDGES;

    float* y; cudaGetSymbolAddress((void**)&y, g_y);
    float* z; cudaGetSymbolAddress((void**)&z, g_z);

    // CSR build (by dst)
    zero_cnt_kernel<<<(N_NODES + 255) / 256, 256>>>();
    hist_kernel<<<(N_EDGES + 255) / 256, 256>>>(dst);
    scan_kernel<<<1, 1024>>>();
    reorder_kernel<<<(N_EDGES + 255) / 256, 256>>>(src, dst);

    // y = x @ W1 (overlaps CSR build in-stream order; independent of it)
    gemm_x_kernel<<<N_NODES / 4, 256>>>(x, W1, y);

    // layer 1: gather + relu + @W2 fused
    layer1_kernel<<<N_NODES / 8, 256>>>(b1, W2, z);

    // layer 2: gather + bias + log_softmax fused
    layer2_kernel<<<N_NODES / 8, 256>>>(b2, out);
}

// round 5
// speedup vs baseline: 2.2842x; 2.2842x over previous
#include <cuda_runtime.h>

#define N_NODES 50000
#define N_EDGES 800000
#define IN_F 96
#define HID 64
#define N_CLS 32

// Scratch (__device__ globals, allocation-free rule)
__device__ __align__(16) float g_y[N_NODES * HID];       // x @ W1        (12.8 MB)
__device__ __align__(16) float g_agg1[N_NODES * HID];    // scatter of y  (12.8 MB)
__device__ __align__(16) float g_z[N_NODES * N_CLS];     // relu(.)@W2    ( 6.4 MB)
__device__ __align__(16) float g_agg2[N_NODES * N_CLS];  // scatter of z  ( 6.4 MB)

__device__ __forceinline__ void red_add_v4(float* p, float4 v) {
    asm volatile("red.global.add.v4.f32 [%0], {%1,%2,%3,%4};"
                 :: "l"(p), "f"(v.x), "f"(v.y), "f"(v.z), "f"(v.w) : "memory");
}

// Zero agg1 (50000*64) + agg2 (50000*32) = 1.2M float4
__global__ void zero_kernel() {
    const int n1 = N_NODES * HID / 4;
    const int n2 = N_NODES * N_CLS / 4;
    int i = blockIdx.x * blockDim.x + threadIdx.x;
    float4 zv = make_float4(0.f, 0.f, 0.f, 0.f);
    if (i < n1) ((float4*)g_agg1)[i] = zv;
    else if (i < n1 + n2) ((float4*)g_agg2)[i - n1] = zv;
}

// y = x @ W1  [50000 x 64]. Register-tiled: 50 nodes/block, 160 threads,
// thread computes 5 nodes x 4 cols. FMA-bound by design.
__global__ void __launch_bounds__(160) gemm_x_kernel(
        const float* __restrict__ x,
        const float* __restrict__ W1,
        float* __restrict__ Y) {
    __shared__ float xs[50 * 100];    // 50 rows, pad stride 100 floats (20000 B)
    __shared__ float ws[IN_F * HID];  // 24576 B  -> total 43.5 KB static
    int tid = threadIdx.x;

    for (int i = tid; i < IN_F * HID / 4; i += 160)
        ((float4*)ws)[i] = __ldg((const float4*)W1 + i);

    const float4* xg = (const float4*)x + blockIdx.x * 50 * (IN_F / 4);
    for (int i = tid; i < 50 * (IN_F / 4); i += 160) {
        int r = i / (IN_F / 4);
        int c = i - r * (IN_F / 4);
        *(float4*)&xs[r * 100 + c * 4] = __ldg(xg + i);
    }
    __syncthreads();

    int tx = tid & 15;   // col group: cols tx*4 .. tx*4+3
    int ty = tid >> 4;   // node group: 5 nodes each (0..9)
    float acc[5][4];
#pragma unroll
    for (int i = 0; i < 5; ++i)
#pragma unroll
        for (int j = 0; j < 4; ++j) acc[i][j] = 0.f;

    const float* xbase = &xs[ty * 5 * 100];
#pragma unroll 2
    for (int k = 0; k < IN_F; k += 4) {
        float4 wv0 = *(float4*)&ws[(k + 0) * HID + tx * 4];
        float4 wv1 = *(float4*)&ws[(k + 1) * HID + tx * 4];
        float4 wv2 = *(float4*)&ws[(k + 2) * HID + tx * 4];
        float4 wv3 = *(float4*)&ws[(k + 3) * HID + tx * 4];
#pragma unroll
        for (int i = 0; i < 5; ++i) {
            float4 xv = *(float4*)&xbase[i * 100 + k];
            acc[i][0] = fmaf(xv.x, wv0.x, acc[i][0]);
            acc[i][1] = fmaf(xv.x, wv0.y, acc[i][1]);
            acc[i][2] = fmaf(xv.x, wv0.z, acc[i][2]);
            acc[i][3] = fmaf(xv.x, wv0.w, acc[i][3]);
            acc[i][0] = fmaf(xv.y, wv1.x, acc[i][0]);
            acc[i][1] = fmaf(xv.y, wv1.y, acc[i][1]);
            acc[i][2] = fmaf(xv.y, wv1.z, acc[i][2]);
            acc[i][3] = fmaf(xv.y, wv1.w, acc[i][3]);
            acc[i][0] = fmaf(xv.z, wv2.x, acc[i][0]);
            acc[i][1] = fmaf(xv.z, wv2.y, acc[i][1]);
            acc[i][2] = fmaf(xv.z, wv2.z, acc[i][2]);
            acc[i][3] = fmaf(xv.z, wv2.w, acc[i][3]);
            acc[i][0] = fmaf(xv.w, wv3.x, acc[i][0]);
            acc[i][1] = fmaf(xv.w, wv3.y, acc[i][1]);
            acc[i][2] = fmaf(xv.w, wv3.z, acc[i][2]);
            acc[i][3] = fmaf(xv.w, wv3.w, acc[i][3]);
        }
    }
    int n0 = blockIdx.x * 50 + ty * 5;
#pragma unroll
    for (int i = 0; i < 5; ++i)
        *(float4*)&Y[(n0 + i) * HID + tx * 4] =
            make_float4(acc[i][0], acc[i][1], acc[i][2], acc[i][3]);
}

// Scatter-add: out[dst] += feat[src], C float4 chunks per edge, C = 1<<LOGC.
template <int LOGC>
__global__ void scatter_kernel(const float4* __restrict__ feat,
                               float* __restrict__ out,
                               const int* __restrict__ src,
                               const int* __restrict__ dst) {
    const int C = 1 << LOGC;
    int i = blockIdx.x * blockDim.x + threadIdx.x;
    int e = i >> LOGC;
    int c = i & (C - 1);
    int s = __ldg(src + e);
    int d = __ldg(dst + e);
    float4 v = __ldg(feat + s * C + c);
    red_add_v4(out + d * (4 * C) + 4 * c, v);
}

// z = relu(agg1 + b1) @ W2  [50000 x 32]. Register-tiled: 128 nodes/block,
// 256 threads, thread computes 4 nodes x 4 cols. relu+bias fused into staging.
__global__ void __launch_bounds__(256) hidden_kernel(
        const float* __restrict__ agg1,
        const float* __restrict__ b1,
        const float* __restrict__ W2,
        float* __restrict__ Z) {
    __shared__ float as[128 * 68];     // 34816 B (pad stride 68)
    __shared__ float ws[HID * N_CLS];  // 8192 B  -> total 43 KB static
    int tid = threadIdx.x;

    for (int i = tid; i < HID * N_CLS / 4; i += 256)
        ((float4*)ws)[i] = __ldg((const float4*)W2 + i);

    int n0 = blockIdx.x * 128;
    for (int i = tid; i < 128 * (HID / 4); i += 256) {
        int r = i >> 4;          // HID/4 = 16 chunks per row
        int c = i & 15;
        int n = n0 + r;
        float4 v = make_float4(0.f, 0.f, 0.f, 0.f);
        if (n < N_NODES) {
            v = __ldg((const float4*)agg1 + n * (HID / 4) + c);
            float4 b = __ldg((const float4*)b1 + c);
            v.x = fmaxf(v.x + b.x, 0.f);
            v.y = fmaxf(v.y + b.y, 0.f);
            v.z = fmaxf(v.z + b.z, 0.f);
            v.w = fmaxf(v.w + b.w, 0.f);
        }
        *(float4*)&as[r * 68 + c * 4] = v;
    }
    __syncthreads();

    int tx = tid & 7;    // col group (8 x 4 cols = 32)
    int ty = tid >> 3;   // node group (0..31), 4 nodes each
    float acc[4][4];
#pragma unroll
    for (int i = 0; i < 4; ++i)
#pragma unroll
        for (int j = 0; j < 4; ++j) acc[i][j] = 0.f;

    const float* abase = &as[ty * 4 * 68];
#pragma unroll 2
    for (int k = 0; k < HID; k += 4) {
        float4 wv0 = *(float4*)&ws[(k + 0) * N_CLS + tx * 4];
        float4 wv1 = *(float4*)&ws[(k + 1) * N_CLS + tx * 4];
        float4 wv2 = *(float4*)&ws[(k + 2) * N_CLS + tx * 4];
        float4 wv3 = *(float4*)&ws[(k + 3) * N_CLS + tx * 4];
#pragma unroll
        for (int i = 0; i < 4; ++i) {
            float4 xv = *(float4*)&abase[i * 68 + k];
            acc[i][0] = fmaf(xv.x, wv0.x, acc[i][0]);
            acc[i][1] = fmaf(xv.x, wv0.y, acc[i][1]);
            acc[i][2] = fmaf(xv.x, wv0.z, acc[i][2]);
            acc[i][3] = fmaf(xv.x, wv0.w, acc[i][3]);
            acc[i][0] = fmaf(xv.y, wv1.x, acc[i][0]);
            acc[i][1] = fmaf(xv.y, wv1.y, acc[i][1]);
            acc[i][2] = fmaf(xv.y, wv1.z, acc[i][2]);
            acc[i][3] = fmaf(xv.y, wv1.w, acc[i][3]);
            acc[i][0] = fmaf(xv.z, wv2.x, acc[i][0]);
            acc[i][1] = fmaf(xv.z, wv2.y, acc[i][1]);
            acc[i][2] = fmaf(xv.z, wv2.z, acc[i][2]);
            acc[i][3] = fmaf(xv.z, wv2.w, acc[i][3]);
            acc[i][0] = fmaf(xv.w, wv3.x, acc[i][0]);
            acc[i][1] = fmaf(xv.w, wv3.y, acc[i][1]);
            acc[i][2] = fmaf(xv.w, wv3.z, acc[i][2]);
            acc[i][3] = fmaf(xv.w, wv3.w, acc[i][3]);
        }
    }
#pragma unroll
    for (int i = 0; i < 4; ++i) {
        int n = n0 + ty * 4 + i;
        if (n < N_NODES)
            *(float4*)&Z[n * N_CLS + tx * 4] =
                make_float4(acc[i][0], acc[i][1], acc[i][2], acc[i][3]);
    }
}

// out = log_softmax(agg2 + b2). One warp per node (lane = class), 8 nodes/block.
__global__ void lsm_kernel(const float* __restrict__ agg2,
                           const float* __restrict__ b2,
                           float* __restrict__ out) {
    int lane = threadIdx.x & 31;
    int n = blockIdx.x * 8 + (threadIdx.x >> 5);
    float acc = agg2[n * N_CLS + lane] + __ldg(b2 + lane);
    float m = acc;
#pragma unroll
    for (int o = 16; o; o >>= 1) m = fmaxf(m, __shfl_xor_sync(0xffffffffu, m, o));
    float p = __expf(acc - m);
#pragma unroll
    for (int o = 16; o; o >>= 1) p += __shfl_xor_sync(0xffffffffu, p, o);
    out[n * N_CLS + lane] = acc - m - __logf(p);
}

extern "C" void kernel_launch(void* const* d_in, const int* in_sizes, int n_in,
                              void* d_out, int out_size) {
    const float* x  = (const float*)d_in[0];
    const int*   ei = (const int*)d_in[1];   // int32 [2, E]
    const float* W1 = (const float*)d_in[2];
    const float* b1 = (const float*)d_in[3];
    const float* W2 = (const float*)d_in[4];
    const float* b2 = (const float*)d_in[5];
    float* out      = (float*)d_out;

    const int* src = ei;
    const int* dst = ei + N_EDGES;

    float* y;    cudaGetSymbolAddress((void**)&y,    g_y);
    float* agg1; cudaGetSymbolAddress((void**)&agg1, g_agg1);
    float* z;    cudaGetSymbolAddress((void**)&z,    g_z);
    float* agg2; cudaGetSymbolAddress((void**)&agg2, g_agg2);

    // 1. zero accumulators
    zero_kernel<<<(N_NODES * (HID + N_CLS) / 4 + 255) / 256, 256>>>();

    // 2. y = x @ W1  (register-tiled, FMA-bound)
    gemm_x_kernel<<<N_NODES / 50, 160>>>(x, W1, y);

    // 3. agg1[dst] += y[src]   (64 floats = 16 float4 per edge)
    scatter_kernel<4><<<N_EDGES * 16 / 256, 256>>>((const float4*)y, agg1, src, dst);

    // 4. z = relu(agg1 + b1) @ W2  (register-tiled, relu/bias fused in staging)
    hidden_kernel<<<(N_NODES + 127) / 128, 256>>>(agg1, b1, W2, z);

    // 5. agg2[dst] += z[src]   (32 floats = 8 float4 per edge)
    scatter_kernel<3><<<N_EDGES * 8 / 256, 256>>>((const float4*)z, agg2, src, dst);

    // 6. out = log_softmax(agg2 + b2)
    lsm_kernel<<<N_NODES / 8, 256>>>(agg2, b2, out);
}